// round 1
// baseline (speedup 1.0000x reference)
#include <cuda_runtime.h>
#include <cstddef>

// Problem constants
#define IN_DIM    1024
#define N_NEURONS 1024
#define N_DEND    16
#define NNZ       32
#define N_SOMA    (N_NEURONS * N_DEND)   // 16384
#define BATCH     4096
#define SLOPE     0.1f

// Tiling
#define BT   32     // batch tile (lanes = batches)
#define NPC  128    // neurons per CTA
#define MAIN_THREADS 512   // 16 warps

// Scratch (device globals: no allocation allowed in kernel_launch)
// per-soma compacted (weight, xs-word-offset) pairs: 16384*32*8B = 4 MB
__device__ float2 g_wi[(size_t)N_SOMA * NNZ];
// block-diagonal soma->neuron weights: ws[s] = Ws[n][s] (s = n*16+d)
__device__ float  g_ws[N_SOMA];

// ---------------------------------------------------------------------------
// Preprocess 1: compact each soma row of (Wd * dendrite_mask) into 32
// (weight, xs word offset) pairs. One warp per soma row.
// ---------------------------------------------------------------------------
__global__ void compact_kernel(const float* __restrict__ Wd,
                               const float* __restrict__ mask) {
    int s    = blockIdx.x * 8 + (threadIdx.x >> 5);
    int lane = threadIdx.x & 31;
    const float* mrow = mask + (size_t)s * IN_DIM;
    const float* wrow = Wd   + (size_t)s * IN_DIM;

    // defensive zero-fill (nnz is exactly 32 by construction, but stay deterministic)
    g_wi[(size_t)s * NNZ + lane] = make_float2(0.f, __int_as_float(0));
    __syncwarp();

    int count = 0;
    for (int c = 0; c < IN_DIM / 32; c++) {
        int i = c * 32 + lane;
        float m = mrow[i];
        bool on = (m != 0.f);
        unsigned ball = __ballot_sync(0xffffffffu, on);
        if (on) {
            int pos = count + __popc(ball & ((1u << lane) - 1u));
            if (pos < NNZ) {
                // store word offset i*BT so the main kernel does xs[off + lane]
                g_wi[(size_t)s * NNZ + pos] =
                    make_float2(wrow[i] * m, __int_as_float(i * BT));
            }
        }
        count += __popc(ball);
    }
}

// ---------------------------------------------------------------------------
// Preprocess 2: extract block-diagonal Ws entries.
// ---------------------------------------------------------------------------
__global__ void ws_kernel(const float* __restrict__ Ws,
                          const float* __restrict__ smask) {
    int s = blockIdx.x * 256 + threadIdx.x;   // 0 .. 16383
    int n = s >> 4;
    size_t o = (size_t)n * N_SOMA + s;
    g_ws[s] = Ws[o] * smask[o];
}

// ---------------------------------------------------------------------------
// Main fused kernel.
// Grid: (BATCH/BT, N_NEURONS/NPC) = (128, 8). Block: 512 threads (16 warps).
// SMEM: xs[IN_DIM][BT] fp32 = 128 KB (x tile, batch innermost => conflict-free
// gather: warp reads xs[idx][0..31] = 32 consecutive banks).
// Each warp: soma uniform across lanes, lane = batch. Per neuron it walks the
// 16 dendrites, 32 nnz each, applies leaky, reduces with g_ws, applies leaky,
// writes out.
// ---------------------------------------------------------------------------
__global__ void __launch_bounds__(MAIN_THREADS, 1)
dend_main(const float* __restrict__ x,
          const float* __restrict__ bd,
          const float* __restrict__ bs,
          float* __restrict__ out) {
    extern __shared__ float xs[];   // IN_DIM * BT floats
    int lane = threadIdx.x & 31;
    int wid  = threadIdx.x >> 5;
    int b0   = blockIdx.x * BT;
    int n0   = blockIdx.y * NPC;

    // Load x tile transposed: thread (wid, lane) loads row b0+lane, the
    // IN_DIM/16 segment owned by wid, as float4s; stores are conflict-free
    // (lane-contiguous within each xs row).
    {
        const float4* xr = (const float4*)(x + (size_t)(b0 + lane) * IN_DIM);
        #pragma unroll
        for (int k = 0; k < 16; k++) {
            int i4 = wid * 16 + k;
            float4 v = xr[i4];
            int i = i4 * 4;
            xs[(i + 0) * BT + lane] = v.x;
            xs[(i + 1) * BT + lane] = v.y;
            xs[(i + 2) * BT + lane] = v.z;
            xs[(i + 3) * BT + lane] = v.w;
        }
    }
    __syncthreads();

    #pragma unroll 1
    for (int nn = 0; nn < NPC / 16; nn++) {
        int n = n0 + wid * (NPC / 16) + nn;
        const float2* __restrict__ wi = g_wi + (size_t)n * N_DEND * NNZ;
        float acc = __ldg(&bs[n]);

        #pragma unroll 1
        for (int d = 0; d < N_DEND; d++) {
            int s = n * N_DEND + d;
            float h0 = __ldg(&bd[s]);
            float h1 = 0.f;
            const float2* __restrict__ w = wi + d * NNZ;
            // two accumulators: halve the FFMA dependency chain
            #pragma unroll
            for (int j = 0; j < NNZ; j += 2) {
                float2 e0 = __ldg(&w[j]);
                float2 e1 = __ldg(&w[j + 1]);
                float xv0 = xs[__float_as_int(e0.y) + lane];
                float xv1 = xs[__float_as_int(e1.y) + lane];
                h0 = fmaf(e0.x, xv0, h0);
                h1 = fmaf(e1.x, xv1, h1);
            }
            float h = h0 + h1;
            h = fmaxf(h, 0.f) + SLOPE * fminf(h, 0.f);   // leaky
            acc = fmaf(__ldg(&g_ws[s]), h, acc);
        }
        float o = fmaxf(acc, 0.f) + SLOPE * fminf(acc, 0.f);
        out[(size_t)(b0 + lane) * N_NEURONS + n] = o;
    }
}

// ---------------------------------------------------------------------------
// Launch. Inputs (metadata order): x, Wd, bd, Ws, bs, dendrite_mask, soma_mask
// ---------------------------------------------------------------------------
extern "C" void kernel_launch(void* const* d_in, const int* in_sizes, int n_in,
                              void* d_out, int out_size) {
    const float* x     = (const float*)d_in[0];
    const float* Wd    = (const float*)d_in[1];
    const float* bd    = (const float*)d_in[2];
    const float* Ws    = (const float*)d_in[3];
    const float* bs    = (const float*)d_in[4];
    const float* dmask = (const float*)d_in[5];
    const float* smask = (const float*)d_in[6];
    float* out = (float*)d_out;

    // 128 KB dynamic smem for the main kernel (idempotent; not a stream op)
    cudaFuncSetAttribute(dend_main,
                         cudaFuncAttributeMaxDynamicSharedMemorySize,
                         IN_DIM * BT * (int)sizeof(float));

    compact_kernel<<<N_SOMA / 8, 256>>>(Wd, dmask);
    ws_kernel<<<N_SOMA / 256, 256>>>(Ws, smask);

    dim3 grid(BATCH / BT, N_NEURONS / NPC);   // (128, 8)
    dend_main<<<grid, MAIN_THREADS, IN_DIM * BT * sizeof(float)>>>(x, bd, bs, out);
}

// round 2
// speedup vs baseline: 1.0003x; 1.0003x over previous
#include <cuda_runtime.h>
#include <cstddef>

// Problem constants
#define IN_DIM    1024
#define N_NEURONS 1024
#define N_DEND    16
#define NNZ       32
#define N_SOMA    (N_NEURONS * N_DEND)   // 16384
#define BATCH     4096
#define SLOPE     0.1f

// Tiling
#define BT        32     // batch tile (lane = batch)
#define XS_STRIDE 33     // padded stride -> conflict-free transpose store AND gather
#define NPC       64     // neurons per CTA
#define THREADS   1024   // 32 warps
#define OUT_STRIDE 65    // padded out staging stride

// Scratch (device globals; allocation is forbidden in kernel_launch)
// packed pairs: (w0, off0_words, w1, off1_words) per float4; 16384*16*16B = 4 MB
__device__ float4 g_wi4[(size_t)N_SOMA * (NNZ / 2)];
// per-soma metadata: (bd[s], ws[s])
__device__ float2 g_meta[N_SOMA];

// ---------------------------------------------------------------------------
// Preprocess 1: compact each soma row of (Wd * dendrite_mask) into 32
// (weight, xs word offset) pairs. One warp per row, float4 mask loads,
// Wd loaded only at nonzero positions. Output order within a row is
// scrambled — the dot product is order-independent.
// ---------------------------------------------------------------------------
__global__ void compact_kernel(const float* __restrict__ Wd,
                               const float* __restrict__ mask) {
    int s    = blockIdx.x * 8 + (threadIdx.x >> 5);
    int lane = threadIdx.x & 31;
    const float4* m4   = (const float4*)(mask + (size_t)s * IN_DIM);
    const float*  wrow = Wd + (size_t)s * IN_DIM;
    float2* outp = (float2*)&g_wi4[(size_t)s * (NNZ / 2)];

    int cnt = 0;
    #pragma unroll 2
    for (int c = 0; c < IN_DIM / 128; c++) {      // 8 iterations
        float4 m = m4[c * 32 + lane];
        float mv[4] = {m.x, m.y, m.z, m.w};
        #pragma unroll
        for (int k = 0; k < 4; k++) {
            bool on = (mv[k] != 0.f);
            unsigned ball = __ballot_sync(0xffffffffu, on);
            if (on) {
                int pos = cnt + __popc(ball & ((1u << lane) - 1u));
                if (pos < NNZ) {
                    int i = c * 128 + lane * 4 + k;
                    outp[pos] = make_float2(wrow[i] * mv[k],
                                            __int_as_float(i * XS_STRIDE));
                }
            }
            cnt += __popc(ball);
        }
    }
}

// ---------------------------------------------------------------------------
// Preprocess 2: per-soma meta = (bd[s], Ws[n][s] * soma_mask[n][s]).
// ---------------------------------------------------------------------------
__global__ void meta_kernel(const float* __restrict__ Ws,
                            const float* __restrict__ smask,
                            const float* __restrict__ bd) {
    int s = blockIdx.x * 256 + threadIdx.x;     // 0 .. 16383
    int n = s >> 4;
    size_t o = (size_t)n * N_SOMA + s;
    g_meta[s] = make_float2(bd[s], Ws[o] * smask[o]);
}

// ---------------------------------------------------------------------------
// Main fused kernel.
// Grid: (BATCH/BT, N_NEURONS/NPC) = (128, 16). Block: 1024 threads (32 warps).
// SMEM: xs[IN_DIM][BT] fp32, padded stride 33 (132 KB) + out staging (8.3 KB).
// Warp layout: lane = batch, 2 neurons per warp. Per dendrite: 16 packed
// float4 (LDG.128) -> 32 gathers (conflict-free LDS) -> 32 FFMA (2 chains).
// ---------------------------------------------------------------------------
__global__ void __launch_bounds__(THREADS, 1)
dend_main(const float* __restrict__ x,
          const float* __restrict__ bs,
          float* __restrict__ out) {
    extern __shared__ float sm[];
    float* xs = sm;                            // IN_DIM * XS_STRIDE floats
    float* so = sm + IN_DIM * XS_STRIDE;       // BT * OUT_STRIDE floats
    int lane = threadIdx.x & 31;
    int wid  = threadIdx.x >> 5;
    int b0   = blockIdx.x * BT;
    int n0   = blockIdx.y * NPC;

    // Transposed x tile load: warp w owns row b0+w; lanes load consecutive
    // floats (coalesced 128B) and store to padded xs (bank = (i+w)%32,
    // conflict-free).
    {
        const float* xr = x + (size_t)(b0 + wid) * IN_DIM;
        #pragma unroll 8
        for (int c = 0; c < IN_DIM / 32; c++) {
            int i = c * 32 + lane;
            xs[i * XS_STRIDE + wid] = xr[i];
        }
    }
    __syncthreads();

    const float* __restrict__ xl = xs + lane;

    #pragma unroll 1
    for (int nn = 0; nn < NPC / 32; nn++) {    // 2 neurons per warp
        int n = n0 + wid * 2 + nn;
        const float4* __restrict__ wp = g_wi4 + (size_t)n * N_DEND * (NNZ / 2);
        float acc = __ldg(&bs[n]);

        #pragma unroll 1
        for (int d = 0; d < N_DEND; d++) {
            float2 mt = __ldg(&g_meta[n * N_DEND + d]);
            float h0 = mt.x;     // bd
            float h1 = 0.f;
            #pragma unroll 8
            for (int k = 0; k < NNZ / 2; k++) {
                float4 q = __ldg(&wp[d * (NNZ / 2) + k]);
                h0 = fmaf(q.x, xl[__float_as_int(q.y)], h0);
                h1 = fmaf(q.z, xl[__float_as_int(q.w)], h1);
            }
            float h = h0 + h1;
            h = fmaxf(h, 0.f) + SLOPE * fminf(h, 0.f);   // leaky
            acc = fmaf(mt.y, h, acc);                    // ws
        }
        float o = fmaxf(acc, 0.f) + SLOPE * fminf(acc, 0.f);
        so[lane * OUT_STRIDE + wid * 2 + nn] = o;        // bank (lane+nloc)%32
    }
    __syncthreads();

    // Coalesced output: 32 batches x 64 neurons = 2048 floats, 2 per thread.
    int t = threadIdx.x;
    #pragma unroll
    for (int r = 0; r < 2; r++) {
        int e = r * 1024 + t;
        int b = e >> 6, c = e & 63;
        out[(size_t)(b0 + b) * N_NEURONS + n0 + c] = so[b * OUT_STRIDE + c];
    }
}

// ---------------------------------------------------------------------------
// Launch. Inputs (metadata order): x, Wd, bd, Ws, bs, dendrite_mask, soma_mask
// ---------------------------------------------------------------------------
extern "C" void kernel_launch(void* const* d_in, const int* in_sizes, int n_in,
                              void* d_out, int out_size) {
    const float* x     = (const float*)d_in[0];
    const float* Wd    = (const float*)d_in[1];
    const float* bd    = (const float*)d_in[2];
    const float* Ws    = (const float*)d_in[3];
    const float* bs    = (const float*)d_in[4];
    const float* dmask = (const float*)d_in[5];
    const float* smask = (const float*)d_in[6];
    float* out = (float*)d_out;

    const int smem = (IN_DIM * XS_STRIDE + BT * OUT_STRIDE) * (int)sizeof(float);
    cudaFuncSetAttribute(dend_main,
                         cudaFuncAttributeMaxDynamicSharedMemorySize, smem);

    compact_kernel<<<N_SOMA / 8, 256>>>(Wd, dmask);
    meta_kernel<<<N_SOMA / 256, 256>>>(Ws, smask, bd);

    dim3 grid(BATCH / BT, N_NEURONS / NPC);   // (128, 16)
    dend_main<<<grid, THREADS, smem>>>(x, bs, out);
}

// round 4
// speedup vs baseline: 1.3602x; 1.3597x over previous
#include <cuda_runtime.h>
#include <cstddef>

// Problem constants
#define IN_DIM    1024
#define N_NEURONS 1024
#define N_DEND    16
#define NNZ       32
#define N_SOMA    (N_NEURONS * N_DEND)   // 16384
#define BATCH     4096
#define SLOPE     0.1f

// Tiling
#define BT        32       // batches per CTA (lane = batch)
#define XS_STRIDE 33       // padded: conflict-free transpose store AND gather
#define NPC       64       // neurons per CTA
#define THREADS   1024     // 32 warps, 2 neurons per warp
#define SO_STRIDE 68       // out staging stride (floats; rows 16B-aligned)

// SMEM layout (bytes)
#define XS_BYTES  (IN_DIM * XS_STRIDE * 4)            // 135168 (fp32)
#define WB_BYTES  (2 * NPC * N_DEND * 16)             // 32768  (double-buffered float4)
#define MT_BYTES  (NPC * N_DEND * 8)                  // 8192   (float2 meta)
#define SO_BYTES  (BT * SO_STRIDE * 4)                // 8704
#define SMEM_TOTAL (XS_BYTES + WB_BYTES + MT_BYTES + SO_BYTES)   // 184832

// Device scratch (no allocation allowed in kernel_launch)
// g_wi4[n*256 + d*16 + k] = (w0, off0, w1, off1); offsets pre-scaled by XS_STRIDE
__device__ float4 g_wi4[(size_t)N_SOMA * (NNZ / 2)];
__device__ float2 g_meta[N_SOMA];     // (bd[s], ws[s])

#define CP_ASYNC16(dst, src) \
    asm volatile("cp.async.cg.shared.global [%0], [%1], 16;\n" :: "r"(dst), "l"(src))
#define CP_COMMIT() asm volatile("cp.async.commit_group;\n" ::: "memory")
#define CP_WAIT0()  asm volatile("cp.async.wait_group 0;\n" ::: "memory")

// ---------------------------------------------------------------------------
// Preprocess (fused): compact (Wd * dmask) rows into 32 (w, off) pairs
// (one warp per soma row); blocks 0..63 also fill g_meta. Pure fp32.
// ---------------------------------------------------------------------------
__global__ void prep_kernel(const float* __restrict__ Wd,
                            const float* __restrict__ dmask,
                            const float* __restrict__ Ws,
                            const float* __restrict__ smask,
                            const float* __restrict__ bd) {
    if (blockIdx.x < N_SOMA / 256) {
        int s = blockIdx.x * 256 + threadIdx.x;
        int n = s >> 4;
        size_t o = (size_t)n * N_SOMA + s;
        g_meta[s] = make_float2(bd[s], Ws[o] * smask[o]);
    }
    int s    = blockIdx.x * 8 + (threadIdx.x >> 5);
    int lane = threadIdx.x & 31;
    const float4* m4   = (const float4*)(dmask + (size_t)s * IN_DIM);
    const float*  wrow = Wd + (size_t)s * IN_DIM;
    float2* outp = (float2*)&g_wi4[(size_t)s * (NNZ / 2)];

    int cnt = 0;
    #pragma unroll 2
    for (int c = 0; c < IN_DIM / 128; c++) {
        float4 m = m4[c * 32 + lane];
        float mv[4] = {m.x, m.y, m.z, m.w};
        #pragma unroll
        for (int k = 0; k < 4; k++) {
            bool on = (mv[k] != 0.f);
            unsigned ball = __ballot_sync(0xffffffffu, on);
            if (on) {
                int pos = cnt + __popc(ball & ((1u << lane) - 1u));
                if (pos < NNZ) {
                    int i = c * 128 + lane * 4 + k;
                    outp[pos] = make_float2(wrow[i] * mv[k],
                                            __int_as_float(i * XS_STRIDE));
                }
            }
            cnt += __popc(ball);
        }
    }
}

// ---------------------------------------------------------------------------
// Main fused kernel. Grid (BATCH/32, N_NEURONS/64) = (128, 16), 1024 threads.
// lane = batch, warp = 2 neurons. Weights staged per-dendrite via cp.async
// double buffer; compute loop is pure SMEM (broadcast LDS.128 + 2 gather
// LDS.32 + 2 FFMA per k). All arithmetic exact fp32.
// ---------------------------------------------------------------------------
__global__ void __launch_bounds__(THREADS, 1)
dend_main(const float* __restrict__ x,
          const float* __restrict__ bs,
          float* __restrict__ out) {
    extern __shared__ char smraw[];
    float*  xs   = (float*)smraw;                          // [IN_DIM][33]
    float4* wbuf = (float4*)(smraw + XS_BYTES);            // [2][NPC*16]
    float2* meta = (float2*)(smraw + XS_BYTES + WB_BYTES); // [NPC*16]
    float*  so   = (float*)(smraw + XS_BYTES + WB_BYTES + MT_BYTES);

    int t = threadIdx.x, lane = t & 31, wid = t >> 5;
    int b0 = blockIdx.x * BT;
    int n0 = blockIdx.y * NPC;

    // x tile transposed: warp wid owns batch row b0+wid; lanes load
    // consecutive floats (coalesced), store conflict-free (stride 33).
    {
        const float* xr = x + (size_t)(b0 + wid) * IN_DIM;
        #pragma unroll 8
        for (int c = 0; c < IN_DIM / 32; c++) {
            int i = c * 32 + lane;
            xs[i * XS_STRIDE + wid] = __ldg(xr + i);
        }
    }
    meta[t] = __ldg(g_meta + (size_t)n0 * N_DEND + t);

    // weight staging: thread t owns (neuron t>>4, k t&15) within each stage
    const float4* wsrc = g_wi4 + (size_t)n0 * (N_DEND * NNZ / 2);
    int wn = t >> 4, wk = t & 15;
    CP_ASYNC16((unsigned)__cvta_generic_to_shared(&wbuf[t]),
               wsrc + wn * 256 + wk);      // stage 0
    CP_COMMIT();

    int nl0 = wid * 2;
    float a0 = __ldg(&bs[n0 + nl0]);
    float a1 = __ldg(&bs[n0 + nl0 + 1]);

    const float* __restrict__ xl = xs + lane;

    __syncthreads();   // xs + meta ready

    #pragma unroll 1
    for (int d = 0; d < N_DEND; d++) {
        CP_WAIT0();
        __syncthreads();                    // stage d visible to all
        if (d < N_DEND - 1) {
            CP_ASYNC16((unsigned)__cvta_generic_to_shared(
                           &wbuf[((d + 1) & 1) * (NPC * 16) + t]),
                       wsrc + wn * 256 + (d + 1) * 16 + wk);
            CP_COMMIT();
        }
        const float4* wb = wbuf + (d & 1) * (NPC * 16);
        #pragma unroll
        for (int nn = 0; nn < 2; nn++) {
            float2 mt = meta[(nl0 + nn) * N_DEND + d];
            float h0 = mt.x, h1 = 0.f;      // bd + 2 FFMA chains
            const float4* __restrict__ wq = wb + (nl0 + nn) * 16;
            #pragma unroll
            for (int k = 0; k < 16; k++) {
                float4 q = wq[k];           // warp-uniform broadcast LDS.128
                h0 = fmaf(q.x, xl[__float_as_int(q.y)], h0);
                h1 = fmaf(q.z, xl[__float_as_int(q.w)], h1);
            }
            float h = h0 + h1;
            h = fmaxf(h, 0.f) + SLOPE * fminf(h, 0.f);   // leaky
            if (nn == 0) a0 = fmaf(mt.y, h, a0);
            else         a1 = fmaf(mt.y, h, a1);
        }
        __syncthreads();                    // protect buf[d&1] before reuse
    }

    float o0 = fmaxf(a0, 0.f) + SLOPE * fminf(a0, 0.f);
    float o1 = fmaxf(a1, 0.f) + SLOPE * fminf(a1, 0.f);
    so[lane * SO_STRIDE + nl0]     = o0;
    so[lane * SO_STRIDE + nl0 + 1] = o1;
    __syncthreads();

    // coalesced output: 32 rows x 64 cols, threads 0..511 write one float4
    if (t < 512) {
        int b = t >> 4, c = (t & 15) * 4;
        float4 v = *(const float4*)&so[b * SO_STRIDE + c];
        *(float4*)&out[(size_t)(b0 + b) * N_NEURONS + n0 + c] = v;
    }
}

// ---------------------------------------------------------------------------
// Launch. Inputs (metadata order): x, Wd, bd, Ws, bs, dendrite_mask, soma_mask
// ---------------------------------------------------------------------------
extern "C" void kernel_launch(void* const* d_in, const int* in_sizes, int n_in,
                              void* d_out, int out_size) {
    const float* x     = (const float*)d_in[0];
    const float* Wd    = (const float*)d_in[1];
    const float* bd    = (const float*)d_in[2];
    const float* Ws    = (const float*)d_in[3];
    const float* bs    = (const float*)d_in[4];
    const float* dmask = (const float*)d_in[5];
    const float* smask = (const float*)d_in[6];
    float* out = (float*)d_out;

    cudaFuncSetAttribute(dend_main,
                         cudaFuncAttributeMaxDynamicSharedMemorySize, SMEM_TOTAL);

    prep_kernel<<<N_SOMA / 8, 256>>>(Wd, dmask, Ws, smask, bd);

    dim3 grid(BATCH / BT, N_NEURONS / NPC);   // (128, 16)
    dend_main<<<grid, THREADS, SMEM_TOTAL>>>(x, bs, out);
}

// round 5
// speedup vs baseline: 1.4504x; 1.0664x over previous
#include <cuda_runtime.h>
#include <cstddef>
#include <cstdint>

// Problem constants
#define IN_DIM    1024
#define N_NEURONS 1024
#define N_DEND    16
#define NNZ       32
#define N_SOMA    (N_NEURONS * N_DEND)   // 16384
#define BATCH     4096
#define SLOPE     0.1f

// Tiling
#define BT        32       // batches per CTA (lane = batch)
#define XS_STRIDE 33       // padded: conflict-free transpose store AND gather
#define NPC       64       // neurons per CTA
#define THREADS   1024     // 32 warps, 2 neurons per warp
#define SO_STRIDE 68       // out staging stride (floats; rows 16B-aligned)

// SMEM layout (bytes)
#define XS_BYTES  (IN_DIM * XS_STRIDE * 4)        // 135168 fp32 x tile
#define WST_BYTES (2 * NPC * 8 * 16)              // 16384: dbl-buf weights (8 float4/neuron)
#define OST_BYTES (2 * NPC * 4 * 16)              // 8192:  dbl-buf offsets (4 uint4/neuron)
#define MT_BYTES  (NPC * N_DEND * 8)              // 8192:  float2 meta
#define SO_BYTES  (BT * SO_STRIDE * 4)            // 8704
#define SMEM_TOTAL (XS_BYTES + WST_BYTES + OST_BYTES + MT_BYTES + SO_BYTES) // 176640

// Device scratch. Weights and u16 offsets in separate streams.
// g_w4[s*8 + j]  : 8 float4 = 32 weights of soma s (compaction order)
// g_off4[s*4 + j]: 4 uint4  = 32 u16 offsets (pre-scaled by XS_STRIDE), same order
__device__ float4 g_w4[(size_t)N_SOMA * 8];
__device__ uint4  g_off4[(size_t)N_SOMA * 4];
__device__ float2 g_meta[N_SOMA];     // (bd[s], ws[s])

#define CP_ASYNC16(dst, src) \
    asm volatile("cp.async.cg.shared.global [%0], [%1], 16;\n" :: "r"(dst), "l"(src))
#define CP_COMMIT() asm volatile("cp.async.commit_group;\n" ::: "memory")
#define CP_WAIT0()  asm volatile("cp.async.wait_group 0;\n" ::: "memory")

// ---------------------------------------------------------------------------
// Preprocess: compact (Wd * dmask) rows into 32 weights (fp32) + 32 u16
// offsets per soma (one warp per row); blocks 0..63 also fill g_meta.
// ---------------------------------------------------------------------------
__global__ void prep_kernel(const float* __restrict__ Wd,
                            const float* __restrict__ dmask,
                            const float* __restrict__ Ws,
                            const float* __restrict__ smask,
                            const float* __restrict__ bd) {
    if (blockIdx.x < N_SOMA / 256) {
        int s = blockIdx.x * 256 + threadIdx.x;
        int n = s >> 4;
        size_t o = (size_t)n * N_SOMA + s;
        g_meta[s] = make_float2(bd[s], Ws[o] * smask[o]);
    }
    int s    = blockIdx.x * 8 + (threadIdx.x >> 5);
    int lane = threadIdx.x & 31;
    const float4* m4   = (const float4*)(dmask + (size_t)s * IN_DIM);
    const float*  wrow = Wd + (size_t)s * IN_DIM;
    float*          wout = (float*)g_w4 + (size_t)s * NNZ;
    unsigned short* oout = (unsigned short*)g_off4 + (size_t)s * NNZ;

    int cnt = 0;
    #pragma unroll 2
    for (int c = 0; c < IN_DIM / 128; c++) {
        float4 m = m4[c * 32 + lane];
        float mv[4] = {m.x, m.y, m.z, m.w};
        #pragma unroll
        for (int k = 0; k < 4; k++) {
            bool on = (mv[k] != 0.f);
            unsigned ball = __ballot_sync(0xffffffffu, on);
            if (on) {
                int pos = cnt + __popc(ball & ((1u << lane) - 1u));
                if (pos < NNZ) {
                    int i = c * 128 + lane * 4 + k;
                    wout[pos] = wrow[i] * mv[k];
                    oout[pos] = (unsigned short)(i * XS_STRIDE);
                }
            }
            cnt += __popc(ball);
        }
    }
}

// ---------------------------------------------------------------------------
// Main fused kernel. Grid (128, 16), 1024 threads (32 warps, 2 neurons/warp,
// lane = batch). Per dendrite: weights + packed u16 offsets staged via
// cp.async double buffer (one __syncthreads per stage). Inner loop per
// 8 k-units: 2 uniform LDS.128 (weights) + 1 uniform LDS.128 (8 offsets)
// + 8 conflict-free gathers + 8 FFMA (4 chains). Exact fp32 arithmetic.
// ---------------------------------------------------------------------------
__global__ void __launch_bounds__(THREADS, 1)
dend_main(const float* __restrict__ x,
          const float* __restrict__ bs,
          float* __restrict__ out) {
    extern __shared__ char smraw[];
    float*  xs   = (float*)smraw;                              // [1024][33]
    float4* wst  = (float4*)(smraw + XS_BYTES);                // [2][64][8]
    uint4*  ost  = (uint4*)(smraw + XS_BYTES + WST_BYTES);     // [2][64][4]
    float2* meta = (float2*)(smraw + XS_BYTES + WST_BYTES + OST_BYTES);
    float*  so   = (float*)(smraw + XS_BYTES + WST_BYTES + OST_BYTES + MT_BYTES);

    int t = threadIdx.x, lane = t & 31, wid = t >> 5;
    int b0 = blockIdx.x * BT;
    int n0 = blockIdx.y * NPC;
    int s0 = n0 * N_DEND;

    // x tile transposed: warp wid owns batch row b0+wid; coalesced loads,
    // conflict-free stride-33 stores.
    {
        const float* xr = x + (size_t)(b0 + wid) * IN_DIM;
        #pragma unroll 8
        for (int c = 0; c < IN_DIM / 32; c++) {
            int i = c * 32 + lane;
            xs[i * XS_STRIDE + wid] = __ldg(xr + i);
        }
    }
    meta[t] = __ldg(g_meta + (size_t)s0 + t);

    // staging roles: t<512 -> weights (neuron t>>3, quad t&7);
    //                t in [512,768) -> offsets (neuron (t-512)>>2, quad (t-512)&3)
    int wn = t >> 3, wj = t & 7;
    int on_ = (t - 512) >> 2, oj = (t - 512) & 3;
    bool is_w = (t < 512), is_o = (t >= 512 && t < 768);

    // prefetch stage 0
    if (is_w)
        CP_ASYNC16((unsigned)__cvta_generic_to_shared(&wst[wn * 8 + wj]),
                   g_w4 + ((size_t)s0 + wn * N_DEND) * 8 + wj);
    if (is_o)
        CP_ASYNC16((unsigned)__cvta_generic_to_shared(&ost[on_ * 4 + oj]),
                   g_off4 + ((size_t)s0 + on_ * N_DEND) * 4 + oj);
    CP_COMMIT();

    int nl0 = wid * 2;
    float a0 = __ldg(&bs[n0 + nl0]);
    float a1 = __ldg(&bs[n0 + nl0 + 1]);

    const float* __restrict__ xl = xs + lane;

    __syncthreads();   // xs + meta ready (stage-0 cp.async still in flight)

    #pragma unroll 1
    for (int d = 0; d < N_DEND; d++) {
        CP_WAIT0();
        __syncthreads();     // stage d visible; buffer (d+1)&1 free (all threads
                             // finished compute d-1 to get here)
        if (d < N_DEND - 1) {
            int nb = (d + 1) & 1;
            if (is_w)
                CP_ASYNC16((unsigned)__cvta_generic_to_shared(
                               &wst[nb * (NPC * 8) + wn * 8 + wj]),
                           g_w4 + ((size_t)s0 + wn * N_DEND + d + 1) * 8 + wj);
            if (is_o)
                CP_ASYNC16((unsigned)__cvta_generic_to_shared(
                               &ost[nb * (NPC * 4) + on_ * 4 + oj]),
                           g_off4 + ((size_t)s0 + on_ * N_DEND + d + 1) * 4 + oj);
            CP_COMMIT();
        }
        const float4* wb = wst + (d & 1) * (NPC * 8);
        const uint4*  ob = ost + (d & 1) * (NPC * 4);

        #pragma unroll
        for (int nn = 0; nn < 2; nn++) {
            int nl = nl0 + nn;
            float2 mt = meta[nl * N_DEND + d];
            const float4* __restrict__ wq = wb + nl * 8;
            const uint4*  __restrict__ oq = ob + nl * 4;
            float h0 = mt.x, h1 = 0.f, h2 = 0.f, h3 = 0.f;
            #pragma unroll
            for (int g = 0; g < 4; g++) {
                uint4  u  = oq[g];            // 8 u16 offsets (uniform)
                float4 wa = wq[2 * g];        // 4 weights (uniform)
                float4 wc = wq[2 * g + 1];
                h0 = fmaf(wa.x, xl[u.x & 0xffff], h0);
                h1 = fmaf(wa.y, xl[u.x >> 16],    h1);
                h2 = fmaf(wa.z, xl[u.y & 0xffff], h2);
                h3 = fmaf(wa.w, xl[u.y >> 16],    h3);
                h0 = fmaf(wc.x, xl[u.z & 0xffff], h0);
                h1 = fmaf(wc.y, xl[u.z >> 16],    h1);
                h2 = fmaf(wc.z, xl[u.w & 0xffff], h2);
                h3 = fmaf(wc.w, xl[u.w >> 16],    h3);
            }
            float h = (h0 + h1) + (h2 + h3);
            h = fmaxf(h, 0.f) + SLOPE * fminf(h, 0.f);   // leaky
            if (nn == 0) a0 = fmaf(mt.y, h, a0);
            else         a1 = fmaf(mt.y, h, a1);
        }
    }

    float o0 = fmaxf(a0, 0.f) + SLOPE * fminf(a0, 0.f);
    float o1 = fmaxf(a1, 0.f) + SLOPE * fminf(a1, 0.f);
    so[lane * SO_STRIDE + nl0]     = o0;
    so[lane * SO_STRIDE + nl0 + 1] = o1;
    __syncthreads();

    // coalesced output: 32 rows x 64 cols, threads 0..511 write one float4
    if (t < 512) {
        int b = t >> 4, c = (t & 15) * 4;
        float4 v = *(const float4*)&so[b * SO_STRIDE + c];
        *(float4*)&out[(size_t)(b0 + b) * N_NEURONS + n0 + c] = v;
    }
}

// ---------------------------------------------------------------------------
// Launch. Inputs (metadata order): x, Wd, bd, Ws, bs, dendrite_mask, soma_mask
// ---------------------------------------------------------------------------
extern "C" void kernel_launch(void* const* d_in, const int* in_sizes, int n_in,
                              void* d_out, int out_size) {
    const float* x     = (const float*)d_in[0];
    const float* Wd    = (const float*)d_in[1];
    const float* bd    = (const float*)d_in[2];
    const float* Ws    = (const float*)d_in[3];
    const float* bs    = (const float*)d_in[4];
    const float* dmask = (const float*)d_in[5];
    const float* smask = (const float*)d_in[6];
    float* out = (float*)d_out;

    cudaFuncSetAttribute(dend_main,
                         cudaFuncAttributeMaxDynamicSharedMemorySize, SMEM_TOTAL);

    prep_kernel<<<N_SOMA / 8, 256>>>(Wd, dmask, Ws, smask, bd);

    dim3 grid(BATCH / BT, N_NEURONS / NPC);   // (128, 16)
    dend_main<<<grid, THREADS, SMEM_TOTAL>>>(x, bs, out);
}

// round 6
// speedup vs baseline: 1.4688x; 1.0127x over previous
#include <cuda_runtime.h>
#include <cstddef>
#include <cstdint>

// Problem constants
#define IN_DIM    1024
#define N_NEURONS 1024
#define N_DEND    16
#define NNZ       32
#define N_SOMA    (N_NEURONS * N_DEND)   // 16384
#define BATCH     4096
#define SLOPE     0.1f

// Tiling
#define BT        32       // batches per CTA (lane = batch)
#define XS_STRIDE 33       // padded: conflict-free transpose store AND gather
#define NPC       64       // neurons per CTA
#define THREADS   1024     // 32 warps, 2 neurons per warp
#define SO_STRIDE 68       // out staging stride

// Packed weight chunks: per (nblock, d), 64 neuron records of 192B
// record = 32 fp32 weights (128B) + 32 u16 offsets (64B), offsets pre-scaled by 33
#define REC_BYTES   192
#define CHUNK_BYTES (NPC * REC_BYTES)    // 12288
#define N_BLOCKS    (N_NEURONS / NPC)    // 16

// SMEM layout (bytes, all 16B aligned)
#define XS_BYTES  (IN_DIM * XS_STRIDE * 4)   // 135168
#define WB_BYTES  (2 * CHUNK_BYTES)          // 24576 double buffer
#define MT_BYTES  (NPC * N_DEND * 8)         // 8192 float2 meta
#define SO_BYTES  (BT * SO_STRIDE * 4)       // 8704
#define MB_BYTES  16                         // 2 mbarriers
#define SMEM_TOTAL (XS_BYTES + WB_BYTES + MT_BYTES + SO_BYTES + MB_BYTES)  // 176656

// Device scratch
__device__ __align__(16) unsigned char g_pack[(size_t)N_BLOCKS * N_DEND * CHUNK_BYTES]; // 3MB
__device__ float2 g_meta[N_SOMA];   // (bd[s], ws[s])

// ---- mbarrier / bulk-copy helpers -----------------------------------------
__device__ __forceinline__ uint32_t smem_u32(const void* p) {
    return (uint32_t)__cvta_generic_to_shared(p);
}
__device__ __forceinline__ void mbar_init(uint32_t mbar, uint32_t cnt) {
    asm volatile("mbarrier.init.shared.b64 [%0], %1;" :: "r"(mbar), "r"(cnt) : "memory");
}
__device__ __forceinline__ void mbar_expect_tx(uint32_t mbar, uint32_t bytes) {
    asm volatile("mbarrier.arrive.expect_tx.shared.b64 _, [%0], %1;"
                 :: "r"(mbar), "r"(bytes) : "memory");
}
__device__ __forceinline__ void bulk_copy(uint32_t dst, const void* src,
                                          uint32_t bytes, uint32_t mbar) {
    asm volatile("cp.async.bulk.shared::cta.global.mbarrier::complete_tx::bytes"
                 " [%0], [%1], %2, [%3];"
                 :: "r"(dst), "l"(src), "r"(bytes), "r"(mbar) : "memory");
}
__device__ __forceinline__ void mbar_wait(uint32_t mbar, uint32_t phase) {
    asm volatile(
        "{\n\t"
        ".reg .pred P;\n"
        "WL_%=:\n\t"
        "mbarrier.try_wait.parity.acquire.cta.shared::cta.b64 P, [%0], %1, 0x989680;\n\t"
        "@P bra WD_%=;\n\t"
        "bra WL_%=;\n"
        "WD_%=:\n\t"
        "}"
        :: "r"(mbar), "r"(phase) : "memory");
}

// ---------------------------------------------------------------------------
// Preprocess: compact (Wd * dmask) rows into packed chunk records
// (one warp per soma row); blocks 0..63 also fill g_meta.
// soma s = n*16+d -> chunk (n/64)*16+d, record slot n%64.
// ---------------------------------------------------------------------------
__global__ void prep_kernel(const float* __restrict__ Wd,
                            const float* __restrict__ dmask,
                            const float* __restrict__ Ws,
                            const float* __restrict__ smask,
                            const float* __restrict__ bd) {
    if (blockIdx.x < N_SOMA / 256) {
        int s = blockIdx.x * 256 + threadIdx.x;
        int n = s >> 4;
        size_t o = (size_t)n * N_SOMA + s;
        g_meta[s] = make_float2(bd[s], Ws[o] * smask[o]);
    }
    int s    = blockIdx.x * 8 + (threadIdx.x >> 5);
    int lane = threadIdx.x & 31;
    int n = s >> 4, d = s & 15;
    unsigned char* rec = g_pack + ((size_t)((n >> 6) * N_DEND + d)) * CHUNK_BYTES
                                + (n & 63) * REC_BYTES;
    float*          wout = (float*)rec;
    unsigned short* oout = (unsigned short*)(rec + 128);

    const float4* m4   = (const float4*)(dmask + (size_t)s * IN_DIM);
    const float*  wrow = Wd + (size_t)s * IN_DIM;

    int cnt = 0;
    #pragma unroll 2
    for (int c = 0; c < IN_DIM / 128; c++) {
        float4 m = m4[c * 32 + lane];
        float mv[4] = {m.x, m.y, m.z, m.w};
        #pragma unroll
        for (int k = 0; k < 4; k++) {
            bool on = (mv[k] != 0.f);
            unsigned ball = __ballot_sync(0xffffffffu, on);
            if (on) {
                int pos = cnt + __popc(ball & ((1u << lane) - 1u));
                if (pos < NNZ) {
                    int i = c * 128 + lane * 4 + k;
                    wout[pos] = wrow[i] * mv[k];
                    oout[pos] = (unsigned short)(i * XS_STRIDE);
                }
            }
            cnt += __popc(ball);
        }
    }
}

// ---------------------------------------------------------------------------
// Main fused kernel. Grid (128, 16), 1024 threads (32 warps, 2 neurons/warp,
// lane = batch). Per-dendrite 12KB weight chunks streamed via cp.async.bulk
// (double buffer, mbarrier completion, 1 barrier/stage). Inner loop per
// 8 k-units: 2 uniform LDS.128 w + 1 uniform LDS.128 offs + 8 conflict-free
// gathers + 8 FFMA (4 chains). Exact fp32.
// ---------------------------------------------------------------------------
__global__ void __launch_bounds__(THREADS, 1)
dend_main(const float* __restrict__ x,
          const float* __restrict__ bs,
          float* __restrict__ out) {
    extern __shared__ char smraw[];
    float*         xs   = (float*)smraw;                               // [1024][33]
    unsigned char* wbuf = (unsigned char*)(smraw + XS_BYTES);          // [2][12288]
    float2*        meta = (float2*)(smraw + XS_BYTES + WB_BYTES);
    float*         so   = (float*)(smraw + XS_BYTES + WB_BYTES + MT_BYTES);
    uint64_t*      mbar = (uint64_t*)(smraw + XS_BYTES + WB_BYTES + MT_BYTES + SO_BYTES);

    int t = threadIdx.x, lane = t & 31, wid = t >> 5;
    int b0 = blockIdx.x * BT;
    int nblock = blockIdx.y;
    int n0 = nblock * NPC;

    uint32_t mb0 = smem_u32(mbar), mb1 = mb0 + 8;
    uint32_t wb_u32 = smem_u32(wbuf);
    const unsigned char* src = g_pack + (size_t)nblock * N_DEND * CHUNK_BYTES;

    if (t == 0) {
        mbar_init(mb0, 1);
        mbar_init(mb1, 1);
        asm volatile("fence.proxy.async.shared::cta;" ::: "memory");
    }

    // x tile transposed: warp wid owns batch row b0+wid; coalesced loads,
    // conflict-free stride-33 stores.
    {
        const float* xr = x + (size_t)(b0 + wid) * IN_DIM;
        #pragma unroll 8
        for (int c = 0; c < IN_DIM / 32; c++) {
            int i = c * 32 + lane;
            xs[i * XS_STRIDE + wid] = __ldg(xr + i);
        }
    }
    meta[t] = __ldg(g_meta + (size_t)n0 * N_DEND + t);

    __syncthreads();   // mbarriers initialized + xs/meta ready

    if (t == 0) {       // kick stage 0
        mbar_expect_tx(mb0, CHUNK_BYTES);
        bulk_copy(wb_u32, src, CHUNK_BYTES, mb0);
    }

    int nl0 = wid * 2;
    float a0 = __ldg(&bs[n0 + nl0]);
    float a1 = __ldg(&bs[n0 + nl0 + 1]);
    const float* __restrict__ xl = xs + lane;

    int ph0 = 0, ph1 = 0;

    #pragma unroll 1
    for (int d = 0; d < N_DEND; d++) {
        int slot = d & 1;
        if (slot == 0) { mbar_wait(mb0, ph0); ph0 ^= 1; }
        else           { mbar_wait(mb1, ph1); ph1 ^= 1; }
        // All threads passed wait(d) => all finished compute(d-1) after this
        // barrier => buffer slot^1 is free to refill.
        __syncthreads();
        if (d < N_DEND - 1 && t == 0) {
            uint32_t m = slot ? mb0 : mb1;
            mbar_expect_tx(m, CHUNK_BYTES);
            bulk_copy(wb_u32 + (slot ^ 1) * CHUNK_BYTES,
                      src + (size_t)(d + 1) * CHUNK_BYTES, CHUNK_BYTES, m);
        }

        const unsigned char* bufb = wbuf + slot * CHUNK_BYTES;
        #pragma unroll
        for (int nn = 0; nn < 2; nn++) {
            int nl = nl0 + nn;
            float2 mt = meta[nl * N_DEND + d];
            const float4* __restrict__ wq = (const float4*)(bufb + nl * REC_BYTES);
            const uint4*  __restrict__ oq = (const uint4*)(bufb + nl * REC_BYTES + 128);
            float h0 = mt.x, h1 = 0.f, h2 = 0.f, h3 = 0.f;
            #pragma unroll
            for (int g = 0; g < 4; g++) {
                uint4  u  = oq[g];            // 8 u16 offsets (uniform, 1 wf)
                float4 wa = wq[2 * g];        // 4 weights (uniform, 1 wf)
                float4 wc = wq[2 * g + 1];
                h0 = fmaf(wa.x, xl[u.x & 0xffff], h0);
                h1 = fmaf(wa.y, xl[u.x >> 16],    h1);
                h2 = fmaf(wa.z, xl[u.y & 0xffff], h2);
                h3 = fmaf(wa.w, xl[u.y >> 16],    h3);
                h0 = fmaf(wc.x, xl[u.z & 0xffff], h0);
                h1 = fmaf(wc.y, xl[u.z >> 16],    h1);
                h2 = fmaf(wc.z, xl[u.w & 0xffff], h2);
                h3 = fmaf(wc.w, xl[u.w >> 16],    h3);
            }
            float h = (h0 + h1) + (h2 + h3);
            h = fmaxf(h, 0.f) + SLOPE * fminf(h, 0.f);   // leaky
            if (nn == 0) a0 = fmaf(mt.y, h, a0);
            else         a1 = fmaf(mt.y, h, a1);
        }
    }

    float o0 = fmaxf(a0, 0.f) + SLOPE * fminf(a0, 0.f);
    float o1 = fmaxf(a1, 0.f) + SLOPE * fminf(a1, 0.f);
    so[lane * SO_STRIDE + nl0]     = o0;
    so[lane * SO_STRIDE + nl0 + 1] = o1;
    __syncthreads();

    // coalesced output: 32 rows x 64 cols, threads 0..511 write one float4
    if (t < 512) {
        int b = t >> 4, c = (t & 15) * 4;
        float4 v = *(const float4*)&so[b * SO_STRIDE + c];
        *(float4*)&out[(size_t)(b0 + b) * N_NEURONS + n0 + c] = v;
    }
}

// ---------------------------------------------------------------------------
// Launch. Inputs (metadata order): x, Wd, bd, Ws, bs, dendrite_mask, soma_mask
// ---------------------------------------------------------------------------
extern "C" void kernel_launch(void* const* d_in, const int* in_sizes, int n_in,
                              void* d_out, int out_size) {
    const float* x     = (const float*)d_in[0];
    const float* Wd    = (const float*)d_in[1];
    const float* bd    = (const float*)d_in[2];
    const float* Ws    = (const float*)d_in[3];
    const float* bs    = (const float*)d_in[4];
    const float* dmask = (const float*)d_in[5];
    const float* smask = (const float*)d_in[6];
    float* out = (float*)d_out;

    cudaFuncSetAttribute(dend_main,
                         cudaFuncAttributeMaxDynamicSharedMemorySize, SMEM_TOTAL);

    prep_kernel<<<N_SOMA / 8, 256>>>(Wd, dmask, Ws, smask, bd);

    dim3 grid(BATCH / BT, N_NEURONS / NPC);   // (128, 16)
    dend_main<<<grid, THREADS, SMEM_TOTAL>>>(x, bs, out);
}

// round 8
// speedup vs baseline: 1.4893x; 1.0139x over previous
#include <cuda_runtime.h>
#include <cstddef>
#include <cstdint>

// Problem constants
#define IN_DIM    1024
#define N_NEURONS 1024
#define N_DEND    16
#define NNZ       32
#define N_SOMA    (N_NEURONS * N_DEND)   // 16384
#define BATCH     4096
#define SLOPE     0.1f

// Tiling
#define BT        32       // batches per CTA (lane = batch)
#define XS_STRIDE 33       // padded: conflict-free transpose store AND gather
#define NPC       64       // neurons per CTA
#define THREADS   1024     // 32 warps, 2 neurons per warp
#define SO_STRIDE 68       // out staging stride

// Per-soma packed record: 32 fp32 weights (128B) + 32 u16 offsets (64B) = 192B
// offsets pre-scaled by XS_STRIDE (word offsets into xs)
#define REC_BYTES 192
#define WSTAGE    4                       // per-warp ring depth
#define WSLOT     (2 * REC_BYTES)         // 384B per stage (2 neurons)
#define WRING     (WSTAGE * WSLOT)        // 1536B per warp

// SMEM layout (bytes)
#define XS_BYTES  (IN_DIM * XS_STRIDE * 4)   // 135168
#define WR_BYTES  (32 * WRING)               // 49152 warp-private rings
#define MT_BYTES  (NPC * N_DEND * 8)         // 8192 float2 meta
#define SO_BYTES  (BT * SO_STRIDE * 4)       // 8704
#define SMEM_TOTAL (XS_BYTES + WR_BYTES + MT_BYTES + SO_BYTES)   // 201216

// Device scratch
__device__ __align__(16) unsigned char g_rec[(size_t)N_SOMA * REC_BYTES]; // 3MB
__device__ float2 g_meta[N_SOMA];   // (bd[s], ws[s])

#define CP_ASYNC16(dst, src) \
    asm volatile("cp.async.cg.shared.global [%0], [%1], 16;\n" :: "r"(dst), "l"(src))
#define CP_COMMIT() asm volatile("cp.async.commit_group;\n" ::: "memory")
#define CP_WAIT2()  asm volatile("cp.async.wait_group 2;\n" ::: "memory")

// ---------------------------------------------------------------------------
// Preprocess: compact (Wd * dmask) rows into per-soma 192B records
// (one warp per soma row); blocks 0..63 also fill g_meta. Pure fp32.
// ---------------------------------------------------------------------------
__global__ void prep_kernel(const float* __restrict__ Wd,
                            const float* __restrict__ dmask,
                            const float* __restrict__ Ws,
                            const float* __restrict__ smask,
                            const float* __restrict__ bd) {
    if (blockIdx.x < N_SOMA / 256) {
        int s = blockIdx.x * 256 + threadIdx.x;
        int n = s >> 4;
        size_t o = (size_t)n * N_SOMA + s;
        g_meta[s] = make_float2(bd[s], Ws[o] * smask[o]);
    }
    int s    = blockIdx.x * 8 + (threadIdx.x >> 5);
    int lane = threadIdx.x & 31;
    unsigned char* rec = g_rec + (size_t)s * REC_BYTES;
    float*          wout = (float*)rec;
    unsigned short* oout = (unsigned short*)(rec + 128);

    const float4* m4   = (const float4*)(dmask + (size_t)s * IN_DIM);
    const float*  wrow = Wd + (size_t)s * IN_DIM;

    int cnt = 0;
    #pragma unroll 2
    for (int c = 0; c < IN_DIM / 128; c++) {
        float4 m = m4[c * 32 + lane];
        float mv[4] = {m.x, m.y, m.z, m.w};
        #pragma unroll
        for (int k = 0; k < 4; k++) {
            bool on = (mv[k] != 0.f);
            unsigned ball = __ballot_sync(0xffffffffu, on);
            if (on) {
                int pos = cnt + __popc(ball & ((1u << lane) - 1u));
                if (pos < NNZ) {
                    int i = c * 128 + lane * 4 + k;
                    wout[pos] = wrow[i] * mv[k];
                    oout[pos] = (unsigned short)(i * XS_STRIDE);
                }
            }
            cnt += __popc(ball);
        }
    }
}

// ---------------------------------------------------------------------------
// Main fused kernel. Grid (128, 16), 1024 threads (32 warps, 2 neurons/warp,
// lane = batch). Each warp streams its own 2 neuron records per dendrite
// through a private 4-slot cp.async ring (lanes 0-23 copy 16B each; one
// commit per stage; wait_group 2 + __syncwarp). NO CTA-wide sync in the
// mainloop -> warps fully decoupled, deadlock impossible. Exact fp32.
// ---------------------------------------------------------------------------
__global__ void __launch_bounds__(THREADS, 1)
dend_main(const float* __restrict__ x,
          const float* __restrict__ bs,
          float* __restrict__ out) {
    extern __shared__ char smraw[];
    float*         xs    = (float*)smraw;                       // [1024][33]
    unsigned char* wring = (unsigned char*)(smraw + XS_BYTES);  // [32][4][384]
    float2*        meta  = (float2*)(smraw + XS_BYTES + WR_BYTES);
    float*         so    = (float*)(smraw + XS_BYTES + WR_BYTES + MT_BYTES);

    int t = threadIdx.x, lane = t & 31, wid = t >> 5;
    int b0 = blockIdx.x * BT;
    int n0 = blockIdx.y * NPC;

    // x tile transposed: warp wid owns batch row b0+wid; coalesced loads,
    // conflict-free stride-33 stores.
    {
        const float* xr = x + (size_t)(b0 + wid) * IN_DIM;
        #pragma unroll 8
        for (int c = 0; c < IN_DIM / 32; c++) {
            int i = c * 32 + lane;
            xs[i * XS_STRIDE + wid] = __ldg(xr + i);
        }
    }
    meta[t] = __ldg(g_meta + (size_t)n0 * N_DEND + t);

    int nl0 = wid * 2;
    // warp-private fetch addressing: lanes 0..11 -> neuron nl0 chunks,
    // lanes 12..23 -> neuron nl0+1 chunks, lanes 24..31 idle.
    int rec   = (lane < 12) ? 0 : 1;
    int chunk = (lane < 12) ? lane : lane - 12;
    const unsigned char* src_base =
        g_rec + ((size_t)(n0 + nl0 + rec) * N_DEND) * REC_BYTES + chunk * 16;
    unsigned char* ring = wring + wid * WRING;
    uint32_t dst_base = (uint32_t)__cvta_generic_to_shared(ring)
                      + rec * REC_BYTES + chunk * 16;
    bool active = (lane < 24);

    // prologue: issue stages 0,1,2 (one commit each)
    #pragma unroll
    for (int s = 0; s < WSTAGE - 1; s++) {
        if (active)
            CP_ASYNC16(dst_base + s * WSLOT, src_base + (size_t)s * REC_BYTES);
        CP_COMMIT();
    }

    float a0 = __ldg(&bs[n0 + nl0]);
    float a1 = __ldg(&bs[n0 + nl0 + 1]);
    const float* __restrict__ xl = xs + lane;

    __syncthreads();   // xs + meta visible to all warps

    #pragma unroll 1
    for (int d = 0; d < N_DEND; d++) {
        CP_WAIT2();        // stage d complete (per-lane)
        __syncwarp();      // cross-lane visibility of stage-d copies
        // issue stage d+3 into slot (d+3)&3 (= (d-1)&3, consumed at iter d-1)
        if (d + WSTAGE - 1 < N_DEND) {
            if (active)
                CP_ASYNC16(dst_base + ((d + WSTAGE - 1) & (WSTAGE - 1)) * WSLOT,
                           src_base + (size_t)(d + WSTAGE - 1) * REC_BYTES);
        }
        CP_COMMIT();       // empty group in tail iterations keeps count uniform

        const unsigned char* bufb = ring + (d & (WSTAGE - 1)) * WSLOT;
        #pragma unroll
        for (int nn = 0; nn < 2; nn++) {
            float2 mt = meta[(nl0 + nn) * N_DEND + d];
            const float4* __restrict__ wq = (const float4*)(bufb + nn * REC_BYTES);
            const uint4*  __restrict__ oq = (const uint4*)(bufb + nn * REC_BYTES + 128);
            float h0 = mt.x, h1 = 0.f, h2 = 0.f, h3 = 0.f;
            #pragma unroll
            for (int g = 0; g < 4; g++) {
                uint4  u  = oq[g];            // 8 u16 offsets (uniform)
                float4 wa = wq[2 * g];        // 4 weights (uniform)
                float4 wc = wq[2 * g + 1];
                h0 = fmaf(wa.x, xl[u.x & 0xffff], h0);
                h1 = fmaf(wa.y, xl[u.x >> 16],    h1);
                h2 = fmaf(wa.z, xl[u.y & 0xffff], h2);
                h3 = fmaf(wa.w, xl[u.y >> 16],    h3);
                h0 = fmaf(wc.x, xl[u.z & 0xffff], h0);
                h1 = fmaf(wc.y, xl[u.z >> 16],    h1);
                h2 = fmaf(wc.z, xl[u.w & 0xffff], h2);
                h3 = fmaf(wc.w, xl[u.w >> 16],    h3);
            }
            float h = (h0 + h1) + (h2 + h3);
            h = fmaxf(h, 0.f) + SLOPE * fminf(h, 0.f);   // leaky
            if (nn == 0) a0 = fmaf(mt.y, h, a0);
            else         a1 = fmaf(mt.y, h, a1);
        }
    }

    float o0 = fmaxf(a0, 0.f) + SLOPE * fminf(a0, 0.f);
    float o1 = fmaxf(a1, 0.f) + SLOPE * fminf(a1, 0.f);
    so[lane * SO_STRIDE + nl0]     = o0;
    so[lane * SO_STRIDE + nl0 + 1] = o1;
    __syncthreads();

    // coalesced output: 32 rows x 64 cols, threads 0..511 write one float4
    if (t < 512) {
        int b = t >> 4, c = (t & 15) * 4;
        float4 v = *(const float4*)&so[b * SO_STRIDE + c];
        *(float4*)&out[(size_t)(b0 + b) * N_NEURONS + n0 + c] = v;
    }
}

// ---------------------------------------------------------------------------
// Launch. Inputs (metadata order): x, Wd, bd, Ws, bs, dendrite_mask, soma_mask
// ---------------------------------------------------------------------------
extern "C" void kernel_launch(void* const* d_in, const int* in_sizes, int n_in,
                              void* d_out, int out_size) {
    const float* x     = (const float*)d_in[0];
    const float* Wd    = (const float*)d_in[1];
    const float* bd    = (const float*)d_in[2];
    const float* Ws    = (const float*)d_in[3];
    const float* bs    = (const float*)d_in[4];
    const float* dmask = (const float*)d_in[5];
    const float* smask = (const float*)d_in[6];
    float* out = (float*)d_out;

    cudaFuncSetAttribute(dend_main,
                         cudaFuncAttributeMaxDynamicSharedMemorySize, SMEM_TOTAL);

    prep_kernel<<<N_SOMA / 8, 256>>>(Wd, dmask, Ws, smask, bd);

    dim3 grid(BATCH / BT, N_NEURONS / NPC);   // (128, 16)
    dend_main<<<grid, THREADS, SMEM_TOTAL>>>(x, bs, out);
}

// round 10
// speedup vs baseline: 1.8505x; 1.2425x over previous
#include <cuda_runtime.h>
#include <cstddef>
#include <cstdint>

// Problem constants
#define IN_DIM    1024
#define N_NEURONS 1024
#define N_DEND    16
#define NNZ       32
#define N_SOMA    (N_NEURONS * N_DEND)   // 16384
#define BATCH     4096
#define SLOPE     0.1f

// Tiling
#define BT        32       // batches per CTA (lane&15 = batch pair)
#define NPC       64       // neurons per CTA
#define THREADS   1024     // 32 warps; half-warp = 1 neuron
#define SO_STRIDE 68

// xs2: float2 rows, 16 pairs + pad -> stride 17 float2 = 136 bytes
#define XS2_ROW_BYTES 136
#define XS2_BYTES  (IN_DIM * XS2_ROW_BYTES)     // 139264

// Per (neuron-pair, dendrite) record: 512B =
//   [OFF_A 32xu32 128B][OFF_B 128B][W_A 32xf32 128B][W_B 128B]
// OFF values are byte offsets i*136 into xs2.
#define REC2       512
#define N_PAIRS    (N_NEURONS / 2)     // 512
#define WSTAGE     3
#define WRING      (WSTAGE * REC2)     // 1536B per warp

#define WR_BYTES  (32 * WRING)             // 49152
#define MT_BYTES  (NPC * N_DEND * 8)       // 8192
#define SO_BYTES  (BT * SO_STRIDE * 4)     // 8704
#define SMEM_TOTAL (XS2_BYTES + WR_BYTES + MT_BYTES + SO_BYTES)   // 205312

// Device scratch
__device__ __align__(16) unsigned char g_rec[(size_t)N_PAIRS * N_DEND * REC2]; // 4MB
__device__ float2 g_meta[N_SOMA];   // (bd[s], ws[s])

#define CP_ASYNC16(dst, src) \
    asm volatile("cp.async.cg.shared.global [%0], [%1], 16;\n" :: "r"(dst), "l"(src))
#define CP_COMMIT() asm volatile("cp.async.commit_group;\n" ::: "memory")
#define CP_WAIT1()  asm volatile("cp.async.wait_group 1;\n" ::: "memory")

// ---------------------------------------------------------------------------
// Preprocess: compact (Wd * dmask) rows into per-(pair,d) 512B records
// (one warp per soma row); blocks 0..63 also fill g_meta. Pure fp32.
// ---------------------------------------------------------------------------
__global__ void prep_kernel(const float* __restrict__ Wd,
                            const float* __restrict__ dmask,
                            const float* __restrict__ Ws,
                            const float* __restrict__ smask,
                            const float* __restrict__ bd) {
    if (blockIdx.x < N_SOMA / 256) {
        int s = blockIdx.x * 256 + threadIdx.x;
        int n = s >> 4;
        size_t o = (size_t)n * N_SOMA + s;
        g_meta[s] = make_float2(bd[s], Ws[o] * smask[o]);
    }
    int s    = blockIdx.x * 8 + (threadIdx.x >> 5);
    int lane = threadIdx.x & 31;
    int n = s >> 4, d = s & 15;
    int npair = n >> 1, sub = n & 1;
    unsigned char* base = g_rec + ((size_t)(npair * N_DEND + d)) * REC2;
    uint32_t* oout = (uint32_t*)(base + sub * 128);
    float*    wout = (float*)(base + 256 + sub * 128);

    const float4* m4   = (const float4*)(dmask + (size_t)s * IN_DIM);
    const float*  wrow = Wd + (size_t)s * IN_DIM;

    int cnt = 0;
    #pragma unroll 2
    for (int c = 0; c < IN_DIM / 128; c++) {
        float4 m = m4[c * 32 + lane];
        float mv[4] = {m.x, m.y, m.z, m.w};
        #pragma unroll
        for (int k = 0; k < 4; k++) {
            bool on = (mv[k] != 0.f);
            unsigned ball = __ballot_sync(0xffffffffu, on);
            if (on) {
                int pos = cnt + __popc(ball & ((1u << lane) - 1u));
                if (pos < NNZ) {
                    int i = c * 128 + lane * 4 + k;
                    wout[pos] = wrow[i] * mv[k];
                    oout[pos] = (uint32_t)(i * XS2_ROW_BYTES);
                }
            }
            cnt += __popc(ball);
        }
    }
}

// ---------------------------------------------------------------------------
// Main fused kernel. Grid (128, 16), 1024 threads. Warp = neuron pair
// (half-warp per neuron), lane&15 = batch pair (float2). Per k-step:
// 1 dual-gather LDS.64 + 2 FFMA; weights/offsets half-uniform LDS.128 from
// warp-private cp.async ring (3 stages). Exact fp32.
// ---------------------------------------------------------------------------
__global__ void __launch_bounds__(THREADS, 1)
dend_main(const float* __restrict__ x,
          const float* __restrict__ bs,
          float* __restrict__ out) {
    extern __shared__ char smraw[];
    char*          xs2   = smraw;                                 // [1024][17 f2]
    unsigned char* wring = (unsigned char*)(smraw + XS2_BYTES);   // [32][3][512]
    float2*        meta  = (float2*)(smraw + XS2_BYTES + WR_BYTES);
    float*         so    = (float*)(smraw + XS2_BYTES + WR_BYTES + MT_BYTES);

    int t = threadIdx.x, lane = t & 31, wid = t >> 5;
    int half = lane >> 4, p = lane & 15;
    int b0 = blockIdx.x * BT;
    int n0 = blockIdx.y * NPC;

    // x tile: 16 batch pairs (b0+2j, b0+2j+1), j=0..15. Warp w owns pair
    // j = w&15 and input-dim half (w>>4)*512: 16 c-iters x 32 lanes = 512
    // rows. LDG coalesced 128B; STS.64 stride-136 (2-way conflict, one-time).
    {
        int pw = wid & 15;
        int ih = (wid >> 4) * (IN_DIM / 2);
        const float* r0 = x + (size_t)(b0 + 2 * pw) * IN_DIM;
        const float* r1 = r0 + IN_DIM;
        #pragma unroll 4
        for (int c = 0; c < IN_DIM / 64; c++) {     // 16 iterations
            int i = ih + c * 32 + lane;
            *(float2*)(xs2 + (size_t)i * XS2_ROW_BYTES + pw * 8) =
                make_float2(__ldg(r0 + i), __ldg(r1 + i));
        }
    }
    meta[t] = __ldg(g_meta + (size_t)n0 * N_DEND + t);

    // warp-private ring: 512B per stage, 32 lanes x 16B each
    int npair = blockIdx.y * 32 + wid;
    const unsigned char* src = g_rec + (size_t)npair * N_DEND * REC2;
    unsigned char* ring = wring + wid * WRING;
    uint32_t ring_u32 = (uint32_t)__cvta_generic_to_shared(ring);

    #pragma unroll
    for (int s = 0; s < WSTAGE - 1; s++) {         // prologue: stages 0,1
        CP_ASYNC16(ring_u32 + s * REC2 + lane * 16,
                   src + (size_t)s * REC2 + lane * 16);
        CP_COMMIT();
    }

    int myn = 2 * wid + half;                      // local neuron 0..63
    float acc0 = __ldg(&bs[n0 + myn]);             // batch b0+2p
    float acc1 = acc0;                             // batch b0+2p+1
    const char* __restrict__ xb = xs2 + p * 8;     // per-lane gather base

    __syncthreads();   // xs2 + meta visible

    #pragma unroll 1
    for (int d = 0; d < N_DEND; d++) {
        CP_WAIT1();        // stage d complete (stage d+1 may pend)
        __syncwarp();
        if (d + 2 < N_DEND) {
            CP_ASYNC16(ring_u32 + ((d + 2) % WSTAGE) * REC2 + lane * 16,
                       src + (size_t)(d + 2) * REC2 + lane * 16);
        }
        CP_COMMIT();       // empty group in tail keeps wait arithmetic uniform

        const unsigned char* bufb = ring + (d % WSTAGE) * REC2;
        const unsigned char* offp = bufb + half * 128;         // my neuron's offs
        const unsigned char* wp   = bufb + 256 + half * 128;   // my neuron's w
        float2 mt = meta[myn * N_DEND + d];

        // chains: h0,h2 -> batch 2p ; h1,h3 -> batch 2p+1 ; bd seeds both
        float h0 = mt.x, h1 = mt.x, h2 = 0.f, h3 = 0.f;
        #pragma unroll
        for (int g = 0; g < 4; g++) {
            uint4  oA = *(const uint4*) (offp + g * 32);
            uint4  oB = *(const uint4*) (offp + g * 32 + 16);
            float4 wA = *(const float4*)(wp   + g * 32);
            float4 wB = *(const float4*)(wp   + g * 32 + 16);
            float2 v;
            v = *(const float2*)(xb + oA.x); h0 = fmaf(wA.x, v.x, h0); h1 = fmaf(wA.x, v.y, h1);
            v = *(const float2*)(xb + oA.y); h2 = fmaf(wA.y, v.x, h2); h3 = fmaf(wA.y, v.y, h3);
            v = *(const float2*)(xb + oA.z); h0 = fmaf(wA.z, v.x, h0); h1 = fmaf(wA.z, v.y, h1);
            v = *(const float2*)(xb + oA.w); h2 = fmaf(wA.w, v.x, h2); h3 = fmaf(wA.w, v.y, h3);
            v = *(const float2*)(xb + oB.x); h0 = fmaf(wB.x, v.x, h0); h1 = fmaf(wB.x, v.y, h1);
            v = *(const float2*)(xb + oB.y); h2 = fmaf(wB.y, v.x, h2); h3 = fmaf(wB.y, v.y, h3);
            v = *(const float2*)(xb + oB.z); h0 = fmaf(wB.z, v.x, h0); h1 = fmaf(wB.z, v.y, h1);
            v = *(const float2*)(xb + oB.w); h2 = fmaf(wB.w, v.x, h2); h3 = fmaf(wB.w, v.y, h3);
        }
        float hA = h0 + h2;    // batch 2p
        float hB = h1 + h3;    // batch 2p+1
        hA = fmaxf(hA, 0.f) + SLOPE * fminf(hA, 0.f);
        hB = fmaxf(hB, 0.f) + SLOPE * fminf(hB, 0.f);
        acc0 = fmaf(mt.y, hA, acc0);
        acc1 = fmaf(mt.y, hB, acc1);
    }

    float o0 = fmaxf(acc0, 0.f) + SLOPE * fminf(acc0, 0.f);
    float o1 = fmaxf(acc1, 0.f) + SLOPE * fminf(acc1, 0.f);
    so[(2 * p)     * SO_STRIDE + myn] = o0;
    so[(2 * p + 1) * SO_STRIDE + myn] = o1;
    __syncthreads();

    // coalesced output: 32 rows x 64 cols, threads 0..511 write one float4
    if (t < 512) {
        int b = t >> 4, c = (t & 15) * 4;
        float4 v = *(const float4*)&so[b * SO_STRIDE + c];
        *(float4*)&out[(size_t)(b0 + b) * N_NEURONS + n0 + c] = v;
    }
}

// ---------------------------------------------------------------------------
// Launch. Inputs (metadata order): x, Wd, bd, Ws, bs, dendrite_mask, soma_mask
// ---------------------------------------------------------------------------
extern "C" void kernel_launch(void* const* d_in, const int* in_sizes, int n_in,
                              void* d_out, int out_size) {
    const float* x     = (const float*)d_in[0];
    const float* Wd    = (const float*)d_in[1];
    const float* bd    = (const float*)d_in[2];
    const float* Ws    = (const float*)d_in[3];
    const float* bs    = (const float*)d_in[4];
    const float* dmask = (const float*)d_in[5];
    const float* smask = (const float*)d_in[6];
    float* out = (float*)d_out;

    cudaFuncSetAttribute(dend_main,
                         cudaFuncAttributeMaxDynamicSharedMemorySize, SMEM_TOTAL);

    prep_kernel<<<N_SOMA / 8, 256>>>(Wd, dmask, Ws, smask, bd);

    dim3 grid(BATCH / BT, N_NEURONS / NPC);   // (128, 16)
    dend_main<<<grid, THREADS, SMEM_TOTAL>>>(x, bs, out);
}

// round 11
// speedup vs baseline: 1.8862x; 1.0193x over previous
#include <cuda_runtime.h>
#include <cstddef>
#include <cstdint>

// Problem constants
#define IN_DIM    1024
#define N_NEURONS 1024
#define N_DEND    16
#define NNZ       32
#define N_SOMA    (N_NEURONS * N_DEND)   // 16384
#define BATCH     4096
#define SLOPE     0.1f

// Tiling
#define BT        32       // batches per CTA (lane&7 = batch quad of 4)
#define NPC       64       // neurons per CTA
#define THREADS   512      // 16 warps; quarter-warp = 1 neuron (4 per warp)
#define SO_STRIDE 68

// xs4: float4 rows, 8 quads + 16B pad -> 144 bytes per input-dim row
#define XS4_ROW_BYTES 144
#define XS4_BYTES  (IN_DIM * XS4_ROW_BYTES)     // 147456

// Per (neuron-quad, dendrite) record: 1024B =
//   [OFF n0..n3: 4 x 32 u32 = 512B][W n0..n3: 4 x 32 f32 = 512B]
// OFF values are byte offsets i*144 into xs4 (quad slot 0 base).
#define REC4       1024
#define N_QUADS    (N_NEURONS / 4)     // 256
#define WSTAGE     3
#define WRING      (WSTAGE * REC4)     // 3072B per warp

#define WR_BYTES  (16 * WRING)             // 49152
#define MT_BYTES  (NPC * N_DEND * 8)       // 8192
#define SO_BYTES  (BT * SO_STRIDE * 4)     // 8704
#define SMEM_TOTAL (XS4_BYTES + WR_BYTES + MT_BYTES + SO_BYTES)   // 213504

// Device scratch
__device__ __align__(16) unsigned char g_rec[(size_t)N_QUADS * N_DEND * REC4]; // 4MB
__device__ float2 g_meta[N_SOMA];   // (bd[s], ws[s])

#define CP_ASYNC16(dst, src) \
    asm volatile("cp.async.cg.shared.global [%0], [%1], 16;\n" :: "r"(dst), "l"(src))
#define CP_COMMIT() asm volatile("cp.async.commit_group;\n" ::: "memory")
#define CP_WAIT1()  asm volatile("cp.async.wait_group 1;\n" ::: "memory")

// ---------------------------------------------------------------------------
// Preprocess: compact (Wd * dmask) rows into per-(quad,d) 1KB records
// (one warp per soma row); blocks 0..63 also fill g_meta. Pure fp32.
// ---------------------------------------------------------------------------
__global__ void prep_kernel(const float* __restrict__ Wd,
                            const float* __restrict__ dmask,
                            const float* __restrict__ Ws,
                            const float* __restrict__ smask,
                            const float* __restrict__ bd) {
    if (blockIdx.x < N_SOMA / 256) {
        int s = blockIdx.x * 256 + threadIdx.x;
        int n = s >> 4;
        size_t o = (size_t)n * N_SOMA + s;
        g_meta[s] = make_float2(bd[s], Ws[o] * smask[o]);
    }
    int s    = blockIdx.x * 8 + (threadIdx.x >> 5);
    int lane = threadIdx.x & 31;
    int n = s >> 4, d = s & 15;
    int quad = n >> 2, sub = n & 3;
    unsigned char* base = g_rec + ((size_t)(quad * N_DEND + d)) * REC4;
    uint32_t* oout = (uint32_t*)(base + sub * 128);
    float*    wout = (float*)(base + 512 + sub * 128);

    const float4* m4   = (const float4*)(dmask + (size_t)s * IN_DIM);
    const float*  wrow = Wd + (size_t)s * IN_DIM;

    int cnt = 0;
    #pragma unroll 2
    for (int c = 0; c < IN_DIM / 128; c++) {
        float4 m = m4[c * 32 + lane];
        float mv[4] = {m.x, m.y, m.z, m.w};
        #pragma unroll
        for (int k = 0; k < 4; k++) {
            bool on = (mv[k] != 0.f);
            unsigned ball = __ballot_sync(0xffffffffu, on);
            if (on) {
                int pos = cnt + __popc(ball & ((1u << lane) - 1u));
                if (pos < NNZ) {
                    int i = c * 128 + lane * 4 + k;
                    wout[pos] = wrow[i] * mv[k];
                    oout[pos] = (uint32_t)(i * XS4_ROW_BYTES);
                }
            }
            cnt += __popc(ball);
        }
    }
}

// ---------------------------------------------------------------------------
// Main fused kernel. Grid (128, 16), 512 threads (16 warps). Warp = neuron
// quad (quarter-warp per neuron), lane&7 = batch quad (float4 of 4 batches).
// Per tap: 1 quad-gather LDS.128 (conflict-free: each 128B run covers all 32
// banks once) + 4 FFMA. Weights/offsets quarter-uniform LDS.128 from a
// warp-private 3-stage cp.async ring. Exact fp32.
// ---------------------------------------------------------------------------
__global__ void __launch_bounds__(THREADS, 1)
dend_main(const float* __restrict__ x,
          const float* __restrict__ bs,
          float* __restrict__ out) {
    extern __shared__ char smraw[];
    char*          xs4   = smraw;                                 // [1024][9 f4]
    unsigned char* wring = (unsigned char*)(smraw + XS4_BYTES);   // [16][3][1024]
    float2*        meta  = (float2*)(smraw + XS4_BYTES + WR_BYTES);
    float*         so    = (float*)(smraw + XS4_BYTES + WR_BYTES + MT_BYTES);

    int t = threadIdx.x, lane = t & 31, wid = t >> 5;        // wid 0..15
    int quarter = lane >> 3, q8 = lane & 7;
    int b0 = blockIdx.x * BT;
    int n0 = blockIdx.y * NPC;

    // x tile: 8 batch quads (b0+4q .. b0+4q+3). Warp w owns quad w&7 and
    // input-dim half (w>>3)*512: 16 c-iters x 32 lanes = its 512 rows.
    // LDG coalesced 128B x4 rows; STS.128 stride-144 (4-way bank conflict,
    // one-time cost accepted).
    {
        int qw = wid & 7;
        int ih = (wid >> 3) * (IN_DIM / 2);
        const float* r0 = x + (size_t)(b0 + 4 * qw) * IN_DIM;
        const float* r1 = r0 + IN_DIM;
        const float* r2 = r1 + IN_DIM;
        const float* r3 = r2 + IN_DIM;
        #pragma unroll 4
        for (int c = 0; c < IN_DIM / 64; c++) {     // 16 iterations
            int i = ih + c * 32 + lane;
            float4 v = make_float4(__ldg(r0 + i), __ldg(r1 + i),
                                   __ldg(r2 + i), __ldg(r3 + i));
            *(float4*)(xs4 + (size_t)i * XS4_ROW_BYTES + qw * 16) = v;
        }
    }
    // meta: 1024 float2, 512 threads load 2 each
    meta[t]       = __ldg(g_meta + (size_t)n0 * N_DEND + t);
    meta[t + 512] = __ldg(g_meta + (size_t)n0 * N_DEND + t + 512);

    // warp-private ring: 1024B per stage, 32 lanes x 2 x 16B
    int myquad = blockIdx.y * 16 + wid;
    const unsigned char* src = g_rec + (size_t)myquad * N_DEND * REC4;
    unsigned char* ring = wring + wid * WRING;
    uint32_t ring_u32 = (uint32_t)__cvta_generic_to_shared(ring);

    #pragma unroll
    for (int s = 0; s < WSTAGE - 1; s++) {          // prologue: stages 0,1
        CP_ASYNC16(ring_u32 + s * REC4 + lane * 16,
                   src + (size_t)s * REC4 + lane * 16);
        CP_ASYNC16(ring_u32 + s * REC4 + 512 + lane * 16,
                   src + (size_t)s * REC4 + 512 + lane * 16);
        CP_COMMIT();
    }

    int myn = wid * 4 + quarter;                    // local neuron 0..63
    float accb = __ldg(&bs[n0 + myn]);
    float acc0 = accb, acc1 = accb, acc2 = accb, acc3 = accb;  // 4 batches
    const char* __restrict__ xq = xs4 + q8 * 16;    // per-lane gather base

    __syncthreads();   // xs4 + meta visible

    #pragma unroll 1
    for (int d = 0; d < N_DEND; d++) {
        CP_WAIT1();        // stage d complete (stage d+1 may pend)
        __syncwarp();      // all lanes done with stage d-1 before overwrite
        if (d + 2 < N_DEND) {
            uint32_t dsts = ring_u32 + ((d + 2) % WSTAGE) * REC4;
            const unsigned char* srcs = src + (size_t)(d + 2) * REC4;
            CP_ASYNC16(dsts + lane * 16,       srcs + lane * 16);
            CP_ASYNC16(dsts + 512 + lane * 16, srcs + 512 + lane * 16);
        }
        CP_COMMIT();       // empty group in tail keeps wait arithmetic uniform

        const unsigned char* bufb = ring + (d % WSTAGE) * REC4;
        const unsigned char* offp = bufb + quarter * 128;        // my offsets
        const unsigned char* wp   = bufb + 512 + quarter * 128;  // my weights
        float2 mt = meta[myn * N_DEND + d];

        // 8 chains: cA (even taps) seeded with bd, cB (odd taps) zero
        float cA0 = mt.x, cA1 = mt.x, cA2 = mt.x, cA3 = mt.x;
        float cB0 = 0.f,  cB1 = 0.f,  cB2 = 0.f,  cB3 = 0.f;
        #pragma unroll
        for (int g = 0; g < 4; g++) {
            uint4  oa = *(const uint4*) (offp + g * 32);
            uint4  ob = *(const uint4*) (offp + g * 32 + 16);
            float4 wa = *(const float4*)(wp   + g * 32);
            float4 wb = *(const float4*)(wp   + g * 32 + 16);
            float4 v;
            v = *(const float4*)(xq + oa.x);
            cA0 = fmaf(wa.x, v.x, cA0); cA1 = fmaf(wa.x, v.y, cA1);
            cA2 = fmaf(wa.x, v.z, cA2); cA3 = fmaf(wa.x, v.w, cA3);
            v = *(const float4*)(xq + oa.y);
            cB0 = fmaf(wa.y, v.x, cB0); cB1 = fmaf(wa.y, v.y, cB1);
            cB2 = fmaf(wa.y, v.z, cB2); cB3 = fmaf(wa.y, v.w, cB3);
            v = *(const float4*)(xq + oa.z);
            cA0 = fmaf(wa.z, v.x, cA0); cA1 = fmaf(wa.z, v.y, cA1);
            cA2 = fmaf(wa.z, v.z, cA2); cA3 = fmaf(wa.z, v.w, cA3);
            v = *(const float4*)(xq + oa.w);
            cB0 = fmaf(wa.w, v.x, cB0); cB1 = fmaf(wa.w, v.y, cB1);
            cB2 = fmaf(wa.w, v.z, cB2); cB3 = fmaf(wa.w, v.w, cB3);
            v = *(const float4*)(xq + ob.x);
            cA0 = fmaf(wb.x, v.x, cA0); cA1 = fmaf(wb.x, v.y, cA1);
            cA2 = fmaf(wb.x, v.z, cA2); cA3 = fmaf(wb.x, v.w, cA3);
            v = *(const float4*)(xq + ob.y);
            cB0 = fmaf(wb.y, v.x, cB0); cB1 = fmaf(wb.y, v.y, cB1);
            cB2 = fmaf(wb.y, v.z, cB2); cB3 = fmaf(wb.y, v.w, cB3);
            v = *(const float4*)(xq + ob.z);
            cA0 = fmaf(wb.z, v.x, cA0); cA1 = fmaf(wb.z, v.y, cA1);
            cA2 = fmaf(wb.z, v.z, cA2); cA3 = fmaf(wb.z, v.w, cA3);
            v = *(const float4*)(xq + ob.w);
            cB0 = fmaf(wb.w, v.x, cB0); cB1 = fmaf(wb.w, v.y, cB1);
            cB2 = fmaf(wb.w, v.z, cB2); cB3 = fmaf(wb.w, v.w, cB3);
        }
        float h0 = cA0 + cB0, h1 = cA1 + cB1, h2 = cA2 + cB2, h3 = cA3 + cB3;
        h0 = fmaxf(h0, 0.f) + SLOPE * fminf(h0, 0.f);
        h1 = fmaxf(h1, 0.f) + SLOPE * fminf(h1, 0.f);
        h2 = fmaxf(h2, 0.f) + SLOPE * fminf(h2, 0.f);
        h3 = fmaxf(h3, 0.f) + SLOPE * fminf(h3, 0.f);
        acc0 = fmaf(mt.y, h0, acc0);
        acc1 = fmaf(mt.y, h1, acc1);
        acc2 = fmaf(mt.y, h2, acc2);
        acc3 = fmaf(mt.y, h3, acc3);
    }

    // stage outputs: batches b0+4*q8+j, neuron myn
    {
        float o;
        o = fmaxf(acc0, 0.f) + SLOPE * fminf(acc0, 0.f); so[(4 * q8 + 0) * SO_STRIDE + myn] = o;
        o = fmaxf(acc1, 0.f) + SLOPE * fminf(acc1, 0.f); so[(4 * q8 + 1) * SO_STRIDE + myn] = o;
        o = fmaxf(acc2, 0.f) + SLOPE * fminf(acc2, 0.f); so[(4 * q8 + 2) * SO_STRIDE + myn] = o;
        o = fmaxf(acc3, 0.f) + SLOPE * fminf(acc3, 0.f); so[(4 * q8 + 3) * SO_STRIDE + myn] = o;
    }
    __syncthreads();

    // coalesced output: 32 rows x 64 cols, 512 threads write one float4 each
    {
        int b = t >> 4, c = (t & 15) * 4;
        float4 v = *(const float4*)&so[b * SO_STRIDE + c];
        *(float4*)&out[(size_t)(b0 + b) * N_NEURONS + n0 + c] = v;
    }
}

// ---------------------------------------------------------------------------
// Launch. Inputs (metadata order): x, Wd, bd, Ws, bs, dendrite_mask, soma_mask
// ---------------------------------------------------------------------------
extern "C" void kernel_launch(void* const* d_in, const int* in_sizes, int n_in,
                              void* d_out, int out_size) {
    const float* x     = (const float*)d_in[0];
    const float* Wd    = (const float*)d_in[1];
    const float* bd    = (const float*)d_in[2];
    const float* Ws    = (const float*)d_in[3];
    const float* bs    = (const float*)d_in[4];
    const float* dmask = (const float*)d_in[5];
    const float* smask = (const float*)d_in[6];
    float* out = (float*)d_out;

    cudaFuncSetAttribute(dend_main,
                         cudaFuncAttributeMaxDynamicSharedMemorySize, SMEM_TOTAL);

    prep_kernel<<<N_SOMA / 8, 256>>>(Wd, dmask, Ws, smask, bd);

    dim3 grid(BATCH / BT, N_NEURONS / NPC);   // (128, 16)
    dend_main<<<grid, THREADS, SMEM_TOTAL>>>(x, bs, out);
}

// round 12
// speedup vs baseline: 2.1598x; 1.1450x over previous
#include <cuda_runtime.h>
#include <cstddef>
#include <cstdint>

// Problem constants
#define IN_DIM    1024
#define N_NEURONS 1024
#define N_DEND    16
#define NNZ       32
#define N_SOMA    (N_NEURONS * N_DEND)   // 16384
#define BATCH     4096
#define SLOPE     0.1f

// Tiling
#define BT        32       // batches per CTA (lane&7 = batch quad of 4)
#define NPC       64       // neurons per CTA
#define THREADS   512      // 16 warps; quarter-warp = 1 neuron (4 per warp)
#define SO_STRIDE 68

// xs4: float4 rows, 8 quads + 16B pad -> 144 bytes per input-dim row
#define XS4_ROW_BYTES 144
#define XS4_BYTES  (IN_DIM * XS4_ROW_BYTES)     // 147456

// Per (neuron-quad, dendrite) record: 1024B =
//   [OFF q0..q3: 4 x 128B][W q0..q3: 4 x 128B]
// Within quarter q's 128B block, 16B chunk c lives at slot ((c+q)&7)*16
// (bank stagger: one warp-load of chunk c hits 4 distinct bank groups -> 1 wf).
// OFF values are byte offsets i*144 into xs4 (quad slot 0 base).
#define REC4       1024
#define N_QUADS    (N_NEURONS / 4)     // 256
#define WSTAGE     3
#define WRING      (WSTAGE * REC4)     // 3072B per warp

#define WR_BYTES  (16 * WRING)             // 49152
#define MT_BYTES  (NPC * N_DEND * 8)       // 8192
#define SO_BYTES  (BT * SO_STRIDE * 4)     // 8704
#define SMEM_TOTAL (XS4_BYTES + WR_BYTES + MT_BYTES + SO_BYTES)   // 213504

// Device scratch
__device__ __align__(16) unsigned char g_rec[(size_t)N_QUADS * N_DEND * REC4]; // 4MB
__device__ float2 g_meta[N_SOMA];   // (bd[s], ws[s])

#define CP_ASYNC16(dst, src) \
    asm volatile("cp.async.cg.shared.global [%0], [%1], 16;\n" :: "r"(dst), "l"(src))
#define CP_COMMIT() asm volatile("cp.async.commit_group;\n" ::: "memory")
#define CP_WAIT1()  asm volatile("cp.async.wait_group 1;\n" ::: "memory")

// ---------------------------------------------------------------------------
// Preprocess: compact (Wd * dmask) rows into per-(quad,d) 1KB records with
// bank-staggered chunk slots (one warp per soma row); blocks 0..63 also fill
// g_meta. Pure fp32.
// ---------------------------------------------------------------------------
__global__ void prep_kernel(const float* __restrict__ Wd,
                            const float* __restrict__ dmask,
                            const float* __restrict__ Ws,
                            const float* __restrict__ smask,
                            const float* __restrict__ bd) {
    if (blockIdx.x < N_SOMA / 256) {
        int s = blockIdx.x * 256 + threadIdx.x;
        int n = s >> 4;
        size_t o = (size_t)n * N_SOMA + s;
        g_meta[s] = make_float2(bd[s], Ws[o] * smask[o]);
    }
    int s    = blockIdx.x * 8 + (threadIdx.x >> 5);
    int lane = threadIdx.x & 31;
    int n = s >> 4, d = s & 15;
    int quad = n >> 2, sub = n & 3;
    unsigned char* base = g_rec + ((size_t)(quad * N_DEND + d)) * REC4;
    uint32_t* oout = (uint32_t*)(base + sub * 128);
    float*    wout = (float*)(base + 512 + sub * 128);

    const float4* m4   = (const float4*)(dmask + (size_t)s * IN_DIM);
    const float*  wrow = Wd + (size_t)s * IN_DIM;

    int cnt = 0;
    #pragma unroll 2
    for (int c = 0; c < IN_DIM / 128; c++) {
        float4 m = m4[c * 32 + lane];
        float mv[4] = {m.x, m.y, m.z, m.w};
        #pragma unroll
        for (int k = 0; k < 4; k++) {
            bool on = (mv[k] != 0.f);
            unsigned ball = __ballot_sync(0xffffffffu, on);
            if (on) {
                int pos = cnt + __popc(ball & ((1u << lane) - 1u));
                if (pos < NNZ) {
                    int i = c * 128 + lane * 4 + k;
                    // staggered slot: chunk (pos>>2) -> slot ((pos>>2)+sub)&7
                    int idx = ((((pos >> 2) + sub) & 7) << 2) | (pos & 3);
                    wout[idx] = wrow[i] * mv[k];
                    oout[idx] = (uint32_t)(i * XS4_ROW_BYTES);
                }
            }
            cnt += __popc(ball);
        }
    }
}

// ---------------------------------------------------------------------------
// Main fused kernel. Grid (128, 16), 512 threads (16 warps). Warp = neuron
// quad (quarter-warp per neuron), lane&7 = batch quad (float4 of 4 batches).
// Per tap: 1 quad-gather LDS.128 (4-wf byte floor) + 4 FFMA. Weights/offsets
// via bank-staggered quarter-uniform LDS.128 (1 wf) from a warp-private
// 3-stage cp.async ring. Exact fp32.
// ---------------------------------------------------------------------------
__global__ void __launch_bounds__(THREADS, 1)
dend_main(const float* __restrict__ x,
          const float* __restrict__ bs,
          float* __restrict__ out) {
    extern __shared__ char smraw[];
    char*          xs4   = smraw;                                 // [1024][9 f4]
    unsigned char* wring = (unsigned char*)(smraw + XS4_BYTES);   // [16][3][1024]
    float2*        meta  = (float2*)(smraw + XS4_BYTES + WR_BYTES);
    float*         so    = (float*)(smraw + XS4_BYTES + WR_BYTES + MT_BYTES);

    int t = threadIdx.x, lane = t & 31, wid = t >> 5;        // wid 0..15
    int quarter = lane >> 3, q8 = lane & 7;
    int b0 = blockIdx.x * BT;
    int n0 = blockIdx.y * NPC;

    // x tile: 8 batch quads (b0+4q .. b0+4q+3). Warp w owns quad w&7 and
    // input-dim half (w>>3)*512. LDG coalesced; STS.128 at its 4-wf floor.
    {
        int qw = wid & 7;
        int ih = (wid >> 3) * (IN_DIM / 2);
        const float* r0 = x + (size_t)(b0 + 4 * qw) * IN_DIM;
        const float* r1 = r0 + IN_DIM;
        const float* r2 = r1 + IN_DIM;
        const float* r3 = r2 + IN_DIM;
        #pragma unroll 4
        for (int c = 0; c < IN_DIM / 64; c++) {     // 16 iterations
            int i = ih + c * 32 + lane;
            float4 v = make_float4(__ldg(r0 + i), __ldg(r1 + i),
                                   __ldg(r2 + i), __ldg(r3 + i));
            *(float4*)(xs4 + (size_t)i * XS4_ROW_BYTES + qw * 16) = v;
        }
    }
    // meta: 1024 float2, 512 threads load 2 each
    meta[t]       = __ldg(g_meta + (size_t)n0 * N_DEND + t);
    meta[t + 512] = __ldg(g_meta + (size_t)n0 * N_DEND + t + 512);

    // warp-private ring: 1024B per stage, 32 lanes x 2 x 16B
    int myquad = blockIdx.y * 16 + wid;
    const unsigned char* src = g_rec + (size_t)myquad * N_DEND * REC4;
    unsigned char* ring = wring + wid * WRING;
    uint32_t ring_u32 = (uint32_t)__cvta_generic_to_shared(ring);

    #pragma unroll
    for (int s = 0; s < WSTAGE - 1; s++) {          // prologue: stages 0,1
        CP_ASYNC16(ring_u32 + s * REC4 + lane * 16,
                   src + (size_t)s * REC4 + lane * 16);
        CP_ASYNC16(ring_u32 + s * REC4 + 512 + lane * 16,
                   src + (size_t)s * REC4 + 512 + lane * 16);
        CP_COMMIT();
    }

    int myn = wid * 4 + quarter;                    // local neuron 0..63
    float accb = __ldg(&bs[n0 + myn]);
    float acc0 = accb, acc1 = accb, acc2 = accb, acc3 = accb;  // 4 batches
    const char* __restrict__ xq = xs4 + q8 * 16;    // per-lane gather base

    // staggered chunk byte-offsets for my quarter: chunk c -> ((c+quarter)&7)*16
    int rot[8];
    #pragma unroll
    for (int c = 0; c < 8; c++) rot[c] = ((c + quarter) & 7) * 16;

    __syncthreads();   // xs4 + meta visible

    #pragma unroll 1
    for (int d = 0; d < N_DEND; d++) {
        CP_WAIT1();        // stage d complete (stage d+1 may pend)
        __syncwarp();      // all lanes done with stage d-1 before overwrite
        if (d + 2 < N_DEND) {
            uint32_t dsts = ring_u32 + ((d + 2) % WSTAGE) * REC4;
            const unsigned char* srcs = src + (size_t)(d + 2) * REC4;
            CP_ASYNC16(dsts + lane * 16,       srcs + lane * 16);
            CP_ASYNC16(dsts + 512 + lane * 16, srcs + 512 + lane * 16);
        }
        CP_COMMIT();       // empty group in tail keeps wait arithmetic uniform

        const unsigned char* bufb = ring + (d % WSTAGE) * REC4;
        const unsigned char* offp = bufb + quarter * 128;        // my off block
        const unsigned char* wp   = bufb + 512 + quarter * 128;  // my w block
        float2 mt = meta[myn * N_DEND + d];

        // 8 chains: cA (even taps) seeded with bd, cB (odd taps) zero
        float cA0 = mt.x, cA1 = mt.x, cA2 = mt.x, cA3 = mt.x;
        float cB0 = 0.f,  cB1 = 0.f,  cB2 = 0.f,  cB3 = 0.f;
        #pragma unroll
        for (int g = 0; g < 4; g++) {
            uint4  oa = *(const uint4*) (offp + rot[2 * g]);
            uint4  ob = *(const uint4*) (offp + rot[2 * g + 1]);
            float4 wa = *(const float4*)(wp   + rot[2 * g]);
            float4 wb = *(const float4*)(wp   + rot[2 * g + 1]);
            float4 v;
            v = *(const float4*)(xq + oa.x);
            cA0 = fmaf(wa.x, v.x, cA0); cA1 = fmaf(wa.x, v.y, cA1);
            cA2 = fmaf(wa.x, v.z, cA2); cA3 = fmaf(wa.x, v.w, cA3);
            v = *(const float4*)(xq + oa.y);
            cB0 = fmaf(wa.y, v.x, cB0); cB1 = fmaf(wa.y, v.y, cB1);
            cB2 = fmaf(wa.y, v.z, cB2); cB3 = fmaf(wa.y, v.w, cB3);
            v = *(const float4*)(xq + oa.z);
            cA0 = fmaf(wa.z, v.x, cA0); cA1 = fmaf(wa.z, v.y, cA1);
            cA2 = fmaf(wa.z, v.z, cA2); cA3 = fmaf(wa.z, v.w, cA3);
            v = *(const float4*)(xq + oa.w);
            cB0 = fmaf(wa.w, v.x, cB0); cB1 = fmaf(wa.w, v.y, cB1);
            cB2 = fmaf(wa.w, v.z, cB2); cB3 = fmaf(wa.w, v.w, cB3);
            v = *(const float4*)(xq + ob.x);
            cA0 = fmaf(wb.x, v.x, cA0); cA1 = fmaf(wb.x, v.y, cA1);
            cA2 = fmaf(wb.x, v.z, cA2); cA3 = fmaf(wb.x, v.w, cA3);
            v = *(const float4*)(xq + ob.y);
            cB0 = fmaf(wb.y, v.x, cB0); cB1 = fmaf(wb.y, v.y, cB1);
            cB2 = fmaf(wb.y, v.z, cB2); cB3 = fmaf(wb.y, v.w, cB3);
            v = *(const float4*)(xq + ob.z);
            cA0 = fmaf(wb.z, v.x, cA0); cA1 = fmaf(wb.z, v.y, cA1);
            cA2 = fmaf(wb.z, v.z, cA2); cA3 = fmaf(wb.z, v.w, cA3);
            v = *(const float4*)(xq + ob.w);
            cB0 = fmaf(wb.w, v.x, cB0); cB1 = fmaf(wb.w, v.y, cB1);
            cB2 = fmaf(wb.w, v.z, cB2); cB3 = fmaf(wb.w, v.w, cB3);
        }
        float h0 = cA0 + cB0, h1 = cA1 + cB1, h2 = cA2 + cB2, h3 = cA3 + cB3;
        h0 = fmaxf(h0, 0.f) + SLOPE * fminf(h0, 0.f);
        h1 = fmaxf(h1, 0.f) + SLOPE * fminf(h1, 0.f);
        h2 = fmaxf(h2, 0.f) + SLOPE * fminf(h2, 0.f);
        h3 = fmaxf(h3, 0.f) + SLOPE * fminf(h3, 0.f);
        acc0 = fmaf(mt.y, h0, acc0);
        acc1 = fmaf(mt.y, h1, acc1);
        acc2 = fmaf(mt.y, h2, acc2);
        acc3 = fmaf(mt.y, h3, acc3);
    }

    // stage outputs: batches b0+4*q8+j, neuron myn
    {
        float o;
        o = fmaxf(acc0, 0.f) + SLOPE * fminf(acc0, 0.f); so[(4 * q8 + 0) * SO_STRIDE + myn] = o;
        o = fmaxf(acc1, 0.f) + SLOPE * fminf(acc1, 0.f); so[(4 * q8 + 1) * SO_STRIDE + myn] = o;
        o = fmaxf(acc2, 0.f) + SLOPE * fminf(acc2, 0.f); so[(4 * q8 + 2) * SO_STRIDE + myn] = o;
        o = fmaxf(acc3, 0.f) + SLOPE * fminf(acc3, 0.f); so[(4 * q8 + 3) * SO_STRIDE + myn] = o;
    }
    __syncthreads();

    // coalesced output: 32 rows x 64 cols, 512 threads write one float4 each
    {
        int b = t >> 4, c = (t & 15) * 4;
        float4 v = *(const float4*)&so[b * SO_STRIDE + c];
        *(float4*)&out[(size_t)(b0 + b) * N_NEURONS + n0 + c] = v;
    }
}

// ---------------------------------------------------------------------------
// Launch. Inputs (metadata order): x, Wd, bd, Ws, bs, dendrite_mask, soma_mask
// ---------------------------------------------------------------------------
extern "C" void kernel_launch(void* const* d_in, const int* in_sizes, int n_in,
                              void* d_out, int out_size) {
    const float* x     = (const float*)d_in[0];
    const float* Wd    = (const float*)d_in[1];
    const float* bd    = (const float*)d_in[2];
    const float* Ws    = (const float*)d_in[3];
    const float* bs    = (const float*)d_in[4];
    const float* dmask = (const float*)d_in[5];
    const float* smask = (const float*)d_in[6];
    float* out = (float*)d_out;

    cudaFuncSetAttribute(dend_main,
                         cudaFuncAttributeMaxDynamicSharedMemorySize, SMEM_TOTAL);

    prep_kernel<<<N_SOMA / 8, 256>>>(Wd, dmask, Ws, smask, bd);

    dim3 grid(BATCH / BT, N_NEURONS / NPC);   // (128, 16)
    dend_main<<<grid, THREADS, SMEM_TOTAL>>>(x, bs, out);
}